// round 2
// baseline (speedup 1.0000x reference)
#include <cuda_runtime.h>
#include <math.h>

#define BB 32
#define TT 512
#define DD 768
#define WW 255
#define HH 768
#define G4 3072           // 4*H
#define MR (BB*WW)        // 8160
#define MPAD 8192
#define NNER 9

// ---------------- scratch (static device allocations only) ----------------
__device__ int   g_fidx[MR];
__device__ float g_pooled[MPAD*DD];                    // 25 MB, rows >= MR zeroed
__device__ float g_xg[2][(size_t)MPAD*G4];             // 2 x 100 MB  x@W_ih^T + b
__device__ float g_h[2][BB*HH];
__device__ float g_c[2][BB*HH];
__device__ float g_hs[2][(size_t)MR*HH];               // per-step hidden states
__device__ float g_part[2][2][BB*G4];                  // [kslice][dir] partial h@W_hh^T

typedef unsigned long long ull;

__device__ __forceinline__ void ffma2(ull &c, ull a, ull b){
    asm("fma.rn.f32x2 %0, %1, %2, %0;" : "+l"(c) : "l"(a), "l"(b));
}
__device__ __forceinline__ ull splat2(float x){
    ull r; asm("mov.b64 %0, {%1, %1};" : "=l"(r) : "f"(x)); return r;
}
__device__ __forceinline__ float2 unpack2(ull v){
    float2 f; asm("mov.b64 {%0, %1}, %2;" : "=f"(f.x), "=f"(f.y) : "l"(v)); return f;
}
__device__ __forceinline__ float sigmoidf_(float x){ return 1.0f/(1.0f + expf(-x)); }

// ---------------- init: reset state every replay ----------------
__global__ void k_init(){
    int i  = blockIdx.x*blockDim.x + threadIdx.x;
    int nt = gridDim.x*blockDim.x;
    for (int j=i; j<MR; j+=nt) g_fidx[j] = 0x7fffffff;
    for (int j=i; j<BB*HH; j+=nt){
        g_h[0][j]=0.f; g_h[1][j]=0.f; g_c[0][j]=0.f; g_c[1][j]=0.f;
    }
    for (int j=i; j<(MPAD-MR)*DD; j+=nt) g_pooled[(size_t)MR*DD + j] = 0.f;
}

// ---------------- first-subword index ----------------
__global__ void k_find(const int* __restrict__ wid){
    int i = blockIdx.x*blockDim.x + threadIdx.x;
    if (i < BB*TT){
        int w = wid[i];
        if (w >= 0 && w < WW) atomicMin(&g_fidx[(i/TT)*WW + w], i % TT);
    }
}

// ---------------- gather pooled rows ----------------
__global__ void k_gather(const float* __restrict__ bert){
    int p   = blockIdx.x;                 // p = b*WW + w
    int idx = g_fidx[p];
    if (idx >= TT) idx = 0;               // argmax(all false) == 0 semantics
    int b = p / WW;
    const float4* src = (const float4*)(bert + ((size_t)b*TT + idx)*DD);
    float4*       dst = (float4*)(g_pooled + (size_t)p*DD);
    dst[threadIdx.x] = src[threadIdx.x];  // 192 threads * float4 = 768 floats
}

// ---------------- input-gate GEMM: xg = pooled @ W_ih^T + b ----------------
// C[MPAD x G4] (per dir). Tiles 128x128x16, 256 threads, 8x8 per thread, f32x2.
__global__ __launch_bounds__(256) void k_gemm_xg(
    const float* __restrict__ Wf, const float* __restrict__ Wb,
    const float* __restrict__ bf, const float* __restrict__ bbv)
{
    const float* Wm   = blockIdx.z ? Wb  : Wf;
    const float* bias = blockIdx.z ? bbv : bf;
    float* C = g_xg[blockIdx.z];

    __shared__ float As[16][128];
    __shared__ float Bs[16][128];

    int tid = threadIdx.x;
    int m0 = blockIdx.y*128, n0 = blockIdx.x*128;
    int tm = (tid>>4)*8, tn = (tid&15)*8;

    ull acc[8][4];
    #pragma unroll
    for (int i=0;i<8;i++){ acc[i][0]=0ull; acc[i][1]=0ull; acc[i][2]=0ull; acc[i][3]=0ull; }

    int r   = tid>>1;          // row within tile (0..127), 2 threads per row
    int kqa = (tid&1)*8;       // k start (0 or 8), two float4 each
    const float* Ag = g_pooled + (size_t)(m0+r)*DD;
    const float* Bg = Wm       + (size_t)(n0+r)*DD;

    for (int kt=0; kt<DD; kt+=16){
        float4 a0 = *(const float4*)(Ag + kt + kqa);
        float4 a1 = *(const float4*)(Ag + kt + kqa + 4);
        float4 b0 = *(const float4*)(Bg + kt + kqa);
        float4 b1 = *(const float4*)(Bg + kt + kqa + 4);
        As[kqa+0][r]=a0.x; As[kqa+1][r]=a0.y; As[kqa+2][r]=a0.z; As[kqa+3][r]=a0.w;
        As[kqa+4][r]=a1.x; As[kqa+5][r]=a1.y; As[kqa+6][r]=a1.z; As[kqa+7][r]=a1.w;
        Bs[kqa+0][r]=b0.x; Bs[kqa+1][r]=b0.y; Bs[kqa+2][r]=b0.z; Bs[kqa+3][r]=b0.w;
        Bs[kqa+4][r]=b1.x; Bs[kqa+5][r]=b1.y; Bs[kqa+6][r]=b1.z; Bs[kqa+7][r]=b1.w;
        __syncthreads();
        #pragma unroll
        for (int kk=0; kk<16; kk++){
            float4 av0 = *(const float4*)&As[kk][tm];
            float4 av1 = *(const float4*)&As[kk][tm+4];
            const ull* bq = (const ull*)&Bs[kk][tn];
            ull bp0 = bq[0], bp1 = bq[1], bp2 = bq[2], bp3 = bq[3];
            float am[8] = {av0.x,av0.y,av0.z,av0.w,av1.x,av1.y,av1.z,av1.w};
            #pragma unroll
            for (int i=0;i<8;i++){
                ull as_ = splat2(am[i]);
                ffma2(acc[i][0], as_, bp0);
                ffma2(acc[i][1], as_, bp1);
                ffma2(acc[i][2], as_, bp2);
                ffma2(acc[i][3], as_, bp3);
            }
        }
        __syncthreads();
    }

    #pragma unroll
    for (int i=0;i<8;i++){
        float o[8];
        #pragma unroll
        for (int j=0;j<4;j++){
            float2 v = unpack2(acc[i][j]);
            o[2*j]   = v.x + bias[n0+tn+2*j];
            o[2*j+1] = v.y + bias[n0+tn+2*j+1];
        }
        float4* cp = (float4*)(C + (size_t)(m0+tm+i)*G4 + n0 + tn);
        cp[0] = make_float4(o[0],o[1],o[2],o[3]);
        cp[1] = make_float4(o[4],o[5],o[6],o[7]);
    }
}

// ---------------- per-step recurrent GEMM: part = h @ W_hh^T (split-K) ----------------
// grid (96 n-blocks, 2 kslices, 2 dirs), 128 threads, 32x32 tile, 4m x 2n(f32x2).
__global__ __launch_bounds__(128) void k_step_gemm(
    const float* __restrict__ Whf, const float* __restrict__ Whb)
{
    int d  = blockIdx.z;
    int ks = blockIdx.y;
    int n0 = blockIdx.x*32;
    const float* Wm = d ? Whb : Whf;
    const float* hp = g_h[d];

    __shared__ float hs_s[32][36];   // [k][m], pitch keeps LDS.128 16B-aligned
    __shared__ float ws_s[32][34];   // [k][n], pitch keeps LDS.64  8B-aligned

    int tid = threadIdx.x;
    int m0 = (tid>>4)*4;
    int tn = (tid&15)*2;
    ull acc0=0ull, acc1=0ull, acc2=0ull, acc3=0ull;

    int lrow = tid>>2;       // 0..31
    int lk   = (tid&3)*8;    // 0,8,16,24
    int k0 = ks*384;

    for (int kt=k0; kt<k0+384; kt+=32){
        float4 h0 = *(const float4*)(hp + lrow*HH + kt + lk);
        float4 h1 = *(const float4*)(hp + lrow*HH + kt + lk + 4);
        float4 w0 = *(const float4*)(Wm + (size_t)(n0+lrow)*HH + kt + lk);
        float4 w1 = *(const float4*)(Wm + (size_t)(n0+lrow)*HH + kt + lk + 4);
        hs_s[lk+0][lrow]=h0.x; hs_s[lk+1][lrow]=h0.y; hs_s[lk+2][lrow]=h0.z; hs_s[lk+3][lrow]=h0.w;
        hs_s[lk+4][lrow]=h1.x; hs_s[lk+5][lrow]=h1.y; hs_s[lk+6][lrow]=h1.z; hs_s[lk+7][lrow]=h1.w;
        ws_s[lk+0][lrow]=w0.x; ws_s[lk+1][lrow]=w0.y; ws_s[lk+2][lrow]=w0.z; ws_s[lk+3][lrow]=w0.w;
        ws_s[lk+4][lrow]=w1.x; ws_s[lk+5][lrow]=w1.y; ws_s[lk+6][lrow]=w1.z; ws_s[lk+7][lrow]=w1.w;
        __syncthreads();
        #pragma unroll
        for (int kk=0; kk<32; kk++){
            ull bp = *(const ull*)&ws_s[kk][tn];
            float4 av = *(const float4*)&hs_s[kk][m0];
            ffma2(acc0, splat2(av.x), bp);
            ffma2(acc1, splat2(av.y), bp);
            ffma2(acc2, splat2(av.z), bp);
            ffma2(acc3, splat2(av.w), bp);
        }
        __syncthreads();
    }
    float* out = g_part[ks][d];
    float2 v0 = unpack2(acc0), v1 = unpack2(acc1), v2 = unpack2(acc2), v3 = unpack2(acc3);
    *(float2*)(out + (m0+0)*G4 + n0 + tn) = v0;
    *(float2*)(out + (m0+1)*G4 + n0 + tn) = v1;
    *(float2*)(out + (m0+2)*G4 + n0 + tn) = v2;
    *(float2*)(out + (m0+3)*G4 + n0 + tn) = v3;
}

// ---------------- per-step LSTM cell (torch gate order i,f,g,o) ----------------
__global__ void k_cell(int s){
    int i = blockIdx.x*blockDim.x + threadIdx.x;   // 0 .. 2*BB*HH-1
    int d = i / (BB*HH);
    int r = i - d*(BB*HH);
    int b = r / HH;
    int j = r - b*HH;
    int t = d ? (WW-1-s) : s;

    size_t xb = (size_t)(b*WW + t) * G4;
    int    gb = b*G4;
    const float* xg = g_xg[d];
    const float* p0 = g_part[0][d];
    const float* p1 = g_part[1][d];

    float gi = xg[xb + j       ] + p0[gb + j       ] + p1[gb + j       ];
    float gf = xg[xb + HH + j  ] + p0[gb + HH + j  ] + p1[gb + HH + j  ];
    float gg = xg[xb + 2*HH + j] + p0[gb + 2*HH + j] + p1[gb + 2*HH + j];
    float go = xg[xb + 3*HH + j] + p0[gb + 3*HH + j] + p1[gb + 3*HH + j];

    float c  = g_c[d][r];
    float cn = sigmoidf_(gf)*c + sigmoidf_(gi)*tanhf(gg);
    float h  = sigmoidf_(go)*tanhf(cn);
    g_c[d][r] = cn;
    g_h[d][r] = h;
    g_hs[d][(size_t)(b*WW + t)*HH + j] = h;
}

// ---------------- final: logits, softmax, argmax ----------------
__global__ void k_final(const float* __restrict__ Wl, const float* __restrict__ bl,
                        float* __restrict__ out, int out_size)
{
    int p    = blockIdx.x*(blockDim.x>>5) + (threadIdx.x>>5);
    int lane = threadIdx.x & 31;
    if (p >= MR) return;

    const float* hf = g_hs[0] + (size_t)p*HH;
    const float* hb = g_hs[1] + (size_t)p*HH;

    float lg[NNER];
    #pragma unroll
    for (int n=0;n<NNER;n++) lg[n]=0.f;

    for (int k=lane; k<HH; k+=32){
        float hv  = hf[k];
        float hv2 = hb[k];
        #pragma unroll
        for (int n=0;n<NNER;n++){
            lg[n] += Wl[n*2*HH + k]*hv + Wl[n*2*HH + HH + k]*hv2;
        }
    }
    #pragma unroll
    for (int n=0;n<NNER;n++){
        #pragma unroll
        for (int o=16;o;o>>=1) lg[n] += __shfl_xor_sync(0xffffffffu, lg[n], o);
    }
    if (lane==0){
        float mx = -1e30f;
        #pragma unroll
        for (int n=0;n<NNER;n++){ lg[n] += bl[n]; mx = fmaxf(mx, lg[n]); }
        float e[NNER], sum=0.f;
        #pragma unroll
        for (int n=0;n<NNER;n++){ e[n] = expf(lg[n]-mx); sum += e[n]; }
        float inv = 1.0f/sum;
        int best = 0; float bv = lg[0];
        #pragma unroll
        for (int n=1;n<NNER;n++){ if (lg[n] > bv){ bv = lg[n]; best = n; } }
        #pragma unroll
        for (int n=0;n<NNER;n++) out[p*NNER + n] = e[n]*inv;
        if (out_size >= MR*NNER + MR) out[MR*NNER + p] = (float)best;
    }
}

// ---------------- launch ----------------
extern "C" void kernel_launch(void* const* d_in, const int* in_sizes, int n_in,
                              void* d_out, int out_size)
{
    const float* bert = (const float*)d_in[0];
    const int*   wid  = (const int*)  d_in[1];
    const float* Wihf = (const float*)d_in[2];
    const float* Whhf = (const float*)d_in[3];
    const float* bf   = (const float*)d_in[4];
    const float* Wihb = (const float*)d_in[5];
    const float* Whhb = (const float*)d_in[6];
    const float* bbv  = (const float*)d_in[7];
    const float* Wlin = (const float*)d_in[8];
    const float* blin = (const float*)d_in[9];

    k_init<<<64, 256>>>();
    k_find<<<(BB*TT + 255)/256, 256>>>(wid);
    k_gather<<<MR, 192>>>(bert);
    k_gemm_xg<<<dim3(G4/128, MPAD/128, 2), 256>>>(Wihf, Wihb, bf, bbv);
    for (int s=0; s<WW; s++){
        k_step_gemm<<<dim3(G4/32, 2, 2), 128>>>(Whhf, Whhb);
        k_cell<<<(2*BB*HH)/256, 256>>>(s);
    }
    k_final<<<(MR + 3)/4, 128>>>(Wlin, blin, (float*)d_out, out_size);
}

// round 4
// speedup vs baseline: 1.3283x; 1.3283x over previous
#include <cuda_runtime.h>
#include <math.h>

#define BB 32
#define TT 512
#define DD 768
#define WW 255
#define HH 768
#define G4 3072           // 4*H
#define MR (BB*WW)        // 8160
#define MPAD 8192
#define NNER 9

// persistent LSTM kernel config
#define UPB 12            // hidden units per block
#define CPB 48            // gate columns per block (4*UPB)
#define KCH 192           // k chunk
#define NCH 4             // chunks (KCH*NCH = HH)
#define NBD 64            // blocks per direction
#define NBLK (2*NBD)      // 128 total

// ---------------- scratch ----------------
__device__ int   g_fidx[MR];
__device__ float g_pooled[MPAD*DD];
__device__ float g_xg[2][(size_t)MPAD*G4];
__device__ float g_hstate[2][2][HH][BB];   // [buf][dir][k][m]
__device__ float g_hs[2][(size_t)MR*HH];
__device__ unsigned g_bar_count[2];
__device__ unsigned g_bar_gen[2];

typedef unsigned long long ull;

__device__ __forceinline__ void ffma2(ull &c, ull a, ull b){
    asm("fma.rn.f32x2 %0, %1, %2, %0;" : "+l"(c) : "l"(a), "l"(b));
}
__device__ __forceinline__ ull add2(ull a, ull b){
    ull r; asm("add.rn.f32x2 %0, %1, %2;" : "=l"(r) : "l"(a), "l"(b)); return r;
}
__device__ __forceinline__ ull splat2(float x){
    ull r; asm("mov.b64 %0, {%1, %1};" : "=l"(r) : "f"(x)); return r;
}
__device__ __forceinline__ float2 unpack2(ull v){
    float2 f; asm("mov.b64 {%0, %1}, %2;" : "=f"(f.x), "=f"(f.y) : "l"(v)); return f;
}
__device__ __forceinline__ float sigmoidf_(float x){ return 1.0f/(1.0f + expf(-x)); }

// ---------------- init ----------------
__global__ void k_init(){
    int i  = blockIdx.x*blockDim.x + threadIdx.x;
    int nt = gridDim.x*blockDim.x;
    for (int j=i; j<MR; j+=nt) g_fidx[j] = 0x7fffffff;
    for (int j=i; j<2*HH*BB; j+=nt) (&g_hstate[0][0][0][0])[j] = 0.f;   // buf0, both dirs
    for (int j=i; j<(MPAD-MR)*DD; j+=nt) g_pooled[(size_t)MR*DD + j] = 0.f;
}

// ---------------- first-subword index ----------------
__global__ void k_find(const int* __restrict__ wid){
    int i = blockIdx.x*blockDim.x + threadIdx.x;
    if (i < BB*TT){
        int w = wid[i];
        if (w >= 0 && w < WW) atomicMin(&g_fidx[(i/TT)*WW + w], i % TT);
    }
}

// ---------------- gather pooled rows ----------------
__global__ void k_gather(const float* __restrict__ bert){
    int p   = blockIdx.x;
    int idx = g_fidx[p];
    if (idx >= TT) idx = 0;
    int b = p / WW;
    const float4* src = (const float4*)(bert + ((size_t)b*TT + idx)*DD);
    float4*       dst = (float4*)(g_pooled + (size_t)p*DD);
    dst[threadIdx.x] = src[threadIdx.x];
}

// ---------------- input-gate GEMM (conflict-free B reads) ----------------
__global__ __launch_bounds__(256) void k_gemm_xg(
    const float* __restrict__ Wf, const float* __restrict__ Wb,
    const float* __restrict__ bf, const float* __restrict__ bbv)
{
    const float* Wm   = blockIdx.z ? Wb  : Wf;
    const float* bias = blockIdx.z ? bbv : bf;
    float* C = g_xg[blockIdx.z];

    __shared__ float As[16][128];
    __shared__ float Bs[16][128];

    int tid = threadIdx.x;
    int m0 = blockIdx.y*128, n0 = blockIdx.x*128;
    int tm = (tid>>4)*8;
    int tn2 = (tid&15)*2;               // interleaved: cols tn2 + 32*j

    ull acc[8][4];
    #pragma unroll
    for (int i=0;i<8;i++){ acc[i][0]=0ull; acc[i][1]=0ull; acc[i][2]=0ull; acc[i][3]=0ull; }

    int r   = tid>>1;
    int kqa = (tid&1)*8;
    const float* Ag = g_pooled + (size_t)(m0+r)*DD;
    const float* Bg = Wm       + (size_t)(n0+r)*DD;

    for (int kt=0; kt<DD; kt+=16){
        float4 a0 = *(const float4*)(Ag + kt + kqa);
        float4 a1 = *(const float4*)(Ag + kt + kqa + 4);
        float4 b0 = *(const float4*)(Bg + kt + kqa);
        float4 b1 = *(const float4*)(Bg + kt + kqa + 4);
        As[kqa+0][r]=a0.x; As[kqa+1][r]=a0.y; As[kqa+2][r]=a0.z; As[kqa+3][r]=a0.w;
        As[kqa+4][r]=a1.x; As[kqa+5][r]=a1.y; As[kqa+6][r]=a1.z; As[kqa+7][r]=a1.w;
        Bs[kqa+0][r]=b0.x; Bs[kqa+1][r]=b0.y; Bs[kqa+2][r]=b0.z; Bs[kqa+3][r]=b0.w;
        Bs[kqa+4][r]=b1.x; Bs[kqa+5][r]=b1.y; Bs[kqa+6][r]=b1.z; Bs[kqa+7][r]=b1.w;
        __syncthreads();
        #pragma unroll
        for (int kk=0; kk<16; kk++){
            float4 av0 = *(const float4*)&As[kk][tm];
            float4 av1 = *(const float4*)&As[kk][tm+4];
            ull bp0 = *(const ull*)&Bs[kk][tn2];
            ull bp1 = *(const ull*)&Bs[kk][tn2+32];
            ull bp2 = *(const ull*)&Bs[kk][tn2+64];
            ull bp3 = *(const ull*)&Bs[kk][tn2+96];
            float am[8] = {av0.x,av0.y,av0.z,av0.w,av1.x,av1.y,av1.z,av1.w};
            #pragma unroll
            for (int i=0;i<8;i++){
                ull as_ = splat2(am[i]);
                ffma2(acc[i][0], as_, bp0);
                ffma2(acc[i][1], as_, bp1);
                ffma2(acc[i][2], as_, bp2);
                ffma2(acc[i][3], as_, bp3);
            }
        }
        __syncthreads();
    }

    #pragma unroll
    for (int i=0;i<8;i++){
        float* crow = C + (size_t)(m0+tm+i)*G4 + n0;
        #pragma unroll
        for (int j=0;j<4;j++){
            float2 v = unpack2(acc[i][j]);
            v.x += bias[n0+tn2+32*j];
            v.y += bias[n0+tn2+32*j+1];
            *(float2*)(crow + tn2 + 32*j) = v;
        }
    }
}

// ---------------- grid barrier (per direction, 64 blocks) ----------------
__device__ __forceinline__ void grid_barrier(int d){
    __threadfence();
    __syncthreads();
    if (threadIdx.x == 0){
        unsigned gen = *((volatile unsigned*)&g_bar_gen[d]);
        unsigned a = atomicAdd(&g_bar_count[d], 1u);
        if (a == NBD-1u){
            g_bar_count[d] = 0u;
            __threadfence();
            *((volatile unsigned*)&g_bar_gen[d]) = gen + 1u;
        } else {
            while (*((volatile unsigned*)&g_bar_gen[d]) == gen) { __nanosleep(32); }
            __threadfence();
        }
    }
    __syncthreads();
}

// ---------------- persistent bidirectional LSTM ----------------
// 128 blocks x 256 threads, 1 block/SM guaranteed by 204KB smem.
// Block = (dir, 12 hidden units). Weights resident in smem for all 255 steps.
__global__ __launch_bounds__(256, 1) void k_lstm_pers(
    const float* __restrict__ Whf, const float* __restrict__ Whb)
{
    extern __shared__ float sm[];
    float* ws    = sm;                     // [768][48]      36864 floats
    float* hsbuf = ws + HH*CPB;            // [2][192][32]   12288 floats
    float* gates = hsbuf + 2*KCH*BB;       // [48][32]        1536 floats
    float* cst   = gates + CPB*BB;         // [384]            384 floats

    int tid = threadIdx.x;
    int bid = blockIdx.x;
    int d   = bid >> 6;                    // 0..1
    int u0  = (bid & 63) * UPB;
    const float* Wm = d ? Whb : Whf;

    // stage weights: ws[k][c], c = g*UPB+uu  <- Wm[(g*HH+u0+uu)*HH + k]
    for (int idx = tid; idx < CPB*(HH/4); idx += 256){
        int c  = idx / (HH/4);
        int kq = (idx % (HH/4)) * 4;
        int g = c / UPB, uu = c % UPB;
        float4 w = *(const float4*)(Wm + (size_t)(g*HH + u0 + uu)*HH + kq);
        ws[(kq+0)*CPB + c] = w.x;
        ws[(kq+1)*CPB + c] = w.y;
        ws[(kq+2)*CPB + c] = w.z;
        ws[(kq+3)*CPB + c] = w.w;
    }
    for (int i = tid; i < UPB*BB; i += 256) cst[i] = 0.f;
    __syncthreads();

    int warp  = tid >> 5;        // mg: 4 m-rows
    int lane  = tid & 31;
    int cg    = lane & 7;        // 6 cols
    int ks    = lane >> 3;       // k-split 0..3 (k == ks mod 4)
    int mBase = warp * 4;
    int cBase = cg * 6;

    const float* xg_d = g_xg[d];

    for (int s = 0; s < WW; s++){
        int t = d ? (WW-1-s) : s;
        const float* hsrc = &g_hstate[s&1][d][0][0];
        float*       hdst = &g_hstate[(s+1)&1][d][0][0];

        // prefetch this step's xg gate values (consumed in epilogue)
        float x1[4], x2[4];
        {
            int uu = tid >> 5, m = tid & 31;
            const float* xb = xg_d + (size_t)(m*WW + t)*G4 + u0 + uu;
            x1[0]=xb[0]; x1[1]=xb[HH]; x1[2]=xb[2*HH]; x1[3]=xb[3*HH];
        }
        int i2 = tid + 256;
        if (i2 < UPB*BB){
            int uu = i2 >> 5, m = i2 & 31;
            const float* xb = xg_d + (size_t)(m*WW + t)*G4 + u0 + uu;
            x2[0]=xb[0]; x2[1]=xb[HH]; x2[2]=xb[2*HH]; x2[3]=xb[3*HH];
        }

        ull acc[4][3];
        #pragma unroll
        for (int mi=0;mi<4;mi++){ acc[mi][0]=0ull; acc[mi][1]=0ull; acc[mi][2]=0ull; }

        // stage chunk 0 (L1 bypass: h written by remote SMs)
        float4 st[6];
        {
            const float4* p = (const float4*)hsrc;
            #pragma unroll
            for (int q=0;q<6;q++) st[q] = __ldcg(&p[q*256 + tid]);
        }
        {
            float4* p = (float4*)hsbuf;
            #pragma unroll
            for (int q=0;q<6;q++) p[q*256 + tid] = st[q];
        }
        __syncthreads();

        for (int ch=0; ch<NCH; ch++){
            if (ch < NCH-1){
                const float4* p = (const float4*)(hsrc + (ch+1)*KCH*BB);
                #pragma unroll
                for (int q=0;q<6;q++) st[q] = __ldcg(&p[q*256 + tid]);
            }
            const float* hc = hsbuf + (ch&1)*KCH*BB;
            const float* wc = ws + (ch*KCH)*CPB;
            #pragma unroll 8
            for (int kk=0; kk<KCH/4; kk++){
                int kl = kk*4 + ks;
                float4 hv = *(const float4*)(hc + kl*BB + mBase);
                ull w0 = *(const ull*)(wc + kl*CPB + cBase + 0);
                ull w1 = *(const ull*)(wc + kl*CPB + cBase + 2);
                ull w2 = *(const ull*)(wc + kl*CPB + cBase + 4);
                ull a0 = splat2(hv.x), a1 = splat2(hv.y);
                ull a2 = splat2(hv.z), a3 = splat2(hv.w);
                ffma2(acc[0][0], a0, w0); ffma2(acc[0][1], a0, w1); ffma2(acc[0][2], a0, w2);
                ffma2(acc[1][0], a1, w0); ffma2(acc[1][1], a1, w1); ffma2(acc[1][2], a1, w2);
                ffma2(acc[2][0], a2, w0); ffma2(acc[2][1], a2, w1); ffma2(acc[2][2], a2, w2);
                ffma2(acc[3][0], a3, w0); ffma2(acc[3][1], a3, w1); ffma2(acc[3][2], a3, w2);
            }
            __syncthreads();
            if (ch < NCH-1){
                float4* p = (float4*)(hsbuf + ((ch+1)&1)*KCH*BB);
                #pragma unroll
                for (int q=0;q<6;q++) p[q*256 + tid] = st[q];
                __syncthreads();
            }
        }

        // reduce over k-split (lanes: ks = lane>>3)
        #pragma unroll
        for (int mi=0;mi<4;mi++)
            #pragma unroll
            for (int p=0;p<3;p++){
                ull v = acc[mi][p];
                v = add2(v, __shfl_xor_sync(0xffffffffu, v, 8));
                v = add2(v, __shfl_xor_sync(0xffffffffu, v, 16));
                acc[mi][p] = v;
            }
        if (ks == 0){
            #pragma unroll
            for (int mi=0;mi<4;mi++)
                #pragma unroll
                for (int p=0;p<3;p++){
                    float2 v = unpack2(acc[mi][p]);
                    gates[(cBase+2*p  )*BB + mBase+mi] = v.x;
                    gates[(cBase+2*p+1)*BB + mBase+mi] = v.y;
                }
        }
        __syncthreads();

        // LSTM cell for this block's 384 (unit, batch) pairs
        {
            int uu = tid >> 5, m = tid & 31;
            float gi = gates[(0*UPB+uu)*BB + m] + x1[0];
            float gf = gates[(1*UPB+uu)*BB + m] + x1[1];
            float gg = gates[(2*UPB+uu)*BB + m] + x1[2];
            float go = gates[(3*UPB+uu)*BB + m] + x1[3];
            float c0 = cst[tid];
            float cn = sigmoidf_(gf)*c0 + sigmoidf_(gi)*tanhf(gg);
            float h  = sigmoidf_(go)*tanhf(cn);
            cst[tid] = cn;
            hdst[(u0+uu)*BB + m] = h;
            g_hs[d][(size_t)(m*WW + t)*HH + u0 + uu] = h;
        }
        if (i2 < UPB*BB){
            int uu = i2 >> 5, m = i2 & 31;
            float gi = gates[(0*UPB+uu)*BB + m] + x2[0];
            float gf = gates[(1*UPB+uu)*BB + m] + x2[1];
            float gg = gates[(2*UPB+uu)*BB + m] + x2[2];
            float go = gates[(3*UPB+uu)*BB + m] + x2[3];
            float c0 = cst[i2];
            float cn = sigmoidf_(gf)*c0 + sigmoidf_(gi)*tanhf(gg);
            float h  = sigmoidf_(go)*tanhf(cn);
            cst[i2] = cn;
            hdst[(u0+uu)*BB + m] = h;
            g_hs[d][(size_t)(m*WW + t)*HH + u0 + uu] = h;
        }

        grid_barrier(d);
    }
}

// ---------------- final: logits, softmax, argmax ----------------
__global__ void k_final(const float* __restrict__ Wl, const float* __restrict__ bl,
                        float* __restrict__ out, int out_size)
{
    int p    = blockIdx.x*(blockDim.x>>5) + (threadIdx.x>>5);
    int lane = threadIdx.x & 31;
    if (p >= MR) return;

    const float* hf = g_hs[0] + (size_t)p*HH;
    const float* hb = g_hs[1] + (size_t)p*HH;

    float lg[NNER];
    #pragma unroll
    for (int n=0;n<NNER;n++) lg[n]=0.f;

    for (int k=lane; k<HH; k+=32){
        float hv  = hf[k];
        float hv2 = hb[k];
        #pragma unroll
        for (int n=0;n<NNER;n++){
            lg[n] += Wl[n*2*HH + k]*hv + Wl[n*2*HH + HH + k]*hv2;
        }
    }
    #pragma unroll
    for (int n=0;n<NNER;n++){
        #pragma unroll
        for (int o=16;o;o>>=1) lg[n] += __shfl_xor_sync(0xffffffffu, lg[n], o);
    }
    if (lane==0){
        float mx = -1e30f;
        #pragma unroll
        for (int n=0;n<NNER;n++){ lg[n] += bl[n]; mx = fmaxf(mx, lg[n]); }
        float e[NNER], sum=0.f;
        #pragma unroll
        for (int n=0;n<NNER;n++){ e[n] = expf(lg[n]-mx); sum += e[n]; }
        float inv = 1.0f/sum;
        int best = 0; float bv = lg[0];
        #pragma unroll
        for (int n=1;n<NNER;n++){ if (lg[n] > bv){ bv = lg[n]; best = n; } }
        #pragma unroll
        for (int n=0;n<NNER;n++) out[p*NNER + n] = e[n]*inv;
        if (out_size >= MR*NNER + MR) out[MR*NNER + p] = (float)best;
    }
}

// ---------------- launch ----------------
extern "C" void kernel_launch(void* const* d_in, const int* in_sizes, int n_in,
                              void* d_out, int out_size)
{
    const float* bert = (const float*)d_in[0];
    const int*   wid  = (const int*)  d_in[1];
    const float* Wihf = (const float*)d_in[2];
    const float* Whhf = (const float*)d_in[3];
    const float* bf   = (const float*)d_in[4];
    const float* Wihb = (const float*)d_in[5];
    const float* Whhb = (const float*)d_in[6];
    const float* bbv  = (const float*)d_in[7];
    const float* Wlin = (const float*)d_in[8];
    const float* blin = (const float*)d_in[9];

    static int smem_set = 0;
    const int pers_smem = (HH*CPB + 2*KCH*BB + CPB*BB + UPB*BB) * (int)sizeof(float);
    if (!smem_set){
        cudaFuncSetAttribute(k_lstm_pers, cudaFuncAttributeMaxDynamicSharedMemorySize, pers_smem);
        smem_set = 1;
    }

    k_init<<<64, 256>>>();
    k_find<<<(BB*TT + 255)/256, 256>>>(wid);
    k_gather<<<MR, 192>>>(bert);
    k_gemm_xg<<<dim3(G4/128, MPAD/128, 2), 256>>>(Wihf, Wihb, bf, bbv);
    k_lstm_pers<<<NBLK, 256, pers_smem>>>(Whhf, Whhb);
    k_final<<<(MR + 3)/4, 128>>>(Wlin, blin, (float*)d_out, out_size);
}

// round 6
// speedup vs baseline: 1.6673x; 1.2552x over previous
#include <cuda_runtime.h>
#include <math.h>

#define BB 32
#define TT 512
#define DD 768
#define WW 255
#define HH 768
#define G4 3072           // 4*H
#define MR (BB*WW)        // 8160
#define MPAD 8192
#define NNER 9

// persistent LSTM kernel config
#define UPB 12            // hidden units per block
#define CPB 48            // gate columns per block (4*UPB)
#define KCH 96            // k chunk rows
#define NCH 8             // chunks (KCH*NCH = HH)
#define KPW 12            // k rows per warp per chunk (KCH/8 warps)
#define NBD 64            // blocks per direction
#define NBLK (2*NBD)      // 128 total
#define GPITCH 50         // gred row pitch (per m), breaks 16-way bank conflict
#define GWSZ (BB*GPITCH)  // per-warp gred region (1600 floats)

// ---------------- scratch ----------------
__device__ int   g_fidx[MR];
__device__ float g_pooled[MPAD*DD];
__device__ float g_xg[2][(size_t)MPAD*G4];
__device__ float g_hstate[2][2][HH][BB];   // [buf][dir][k][m]
__device__ float g_hs[2][(size_t)MR*HH];
__device__ int   g_flag[2][NBD];           // per-block step counters

typedef unsigned long long ull;

__device__ __forceinline__ void ffma2(ull &c, ull a, ull b){
    asm("fma.rn.f32x2 %0, %1, %2, %0;" : "+l"(c) : "l"(a), "l"(b));
}
__device__ __forceinline__ ull splat2(float x){
    ull r; asm("mov.b64 %0, {%1, %1};" : "=l"(r) : "f"(x)); return r;
}
__device__ __forceinline__ float2 unpack2(ull v){
    float2 f; asm("mov.b64 {%0, %1}, %2;" : "=f"(f.x), "=f"(f.y) : "l"(v)); return f;
}
__device__ __forceinline__ float sigmoidf_(float x){ return 1.0f/(1.0f + expf(-x)); }

// ---------------- init ----------------
__global__ void k_init(){
    int i  = blockIdx.x*blockDim.x + threadIdx.x;
    int nt = gridDim.x*blockDim.x;
    for (int j=i; j<MR; j+=nt) g_fidx[j] = 0x7fffffff;
    for (int j=i; j<2*HH*BB; j+=nt) (&g_hstate[0][0][0][0])[j] = 0.f;   // buf0, both dirs
    for (int j=i; j<2*NBD; j+=nt) (&g_flag[0][0])[j] = 0;
    for (int j=i; j<(MPAD-MR)*DD; j+=nt) g_pooled[(size_t)MR*DD + j] = 0.f;
}

// ---------------- first-subword index ----------------
__global__ void k_find(const int* __restrict__ wid){
    int i = blockIdx.x*blockDim.x + threadIdx.x;
    if (i < BB*TT){
        int w = wid[i];
        if (w >= 0 && w < WW) atomicMin(&g_fidx[(i/TT)*WW + w], i % TT);
    }
}

// ---------------- gather pooled rows ----------------
__global__ void k_gather(const float* __restrict__ bert){
    int p   = blockIdx.x;
    int idx = g_fidx[p];
    if (idx >= TT) idx = 0;
    int b = p / WW;
    const float4* src = (const float4*)(bert + ((size_t)b*TT + idx)*DD);
    float4*       dst = (float4*)(g_pooled + (size_t)p*DD);
    dst[threadIdx.x] = src[threadIdx.x];
}

// ---------------- input-gate GEMM (double-buffered) ----------------
__global__ __launch_bounds__(256, 2) void k_gemm_xg(
    const float* __restrict__ Wf, const float* __restrict__ Wb,
    const float* __restrict__ bf, const float* __restrict__ bbv)
{
    const float* Wm   = blockIdx.z ? Wb  : Wf;
    const float* bias = blockIdx.z ? bbv : bf;
    float* C = g_xg[blockIdx.z];

    __shared__ float As[2][16][128];
    __shared__ float Bs[2][16][128];

    int tid = threadIdx.x;
    int m0 = blockIdx.y*128, n0 = blockIdx.x*128;
    int tm  = (tid>>4)*8;
    int tn2 = (tid&15)*2;

    ull acc[8][4];
    #pragma unroll
    for (int i=0;i<8;i++){ acc[i][0]=0ull; acc[i][1]=0ull; acc[i][2]=0ull; acc[i][3]=0ull; }

    int r   = tid>>1;
    int kqa = (tid&1)*8;
    const float* Ag = g_pooled + (size_t)(m0+r)*DD + kqa;
    const float* Bg = Wm       + (size_t)(n0+r)*DD + kqa;

    float4 a0 = *(const float4*)(Ag);
    float4 a1 = *(const float4*)(Ag + 4);
    float4 b0 = *(const float4*)(Bg);
    float4 b1 = *(const float4*)(Bg + 4);
    As[0][kqa+0][r]=a0.x; As[0][kqa+1][r]=a0.y; As[0][kqa+2][r]=a0.z; As[0][kqa+3][r]=a0.w;
    As[0][kqa+4][r]=a1.x; As[0][kqa+5][r]=a1.y; As[0][kqa+6][r]=a1.z; As[0][kqa+7][r]=a1.w;
    Bs[0][kqa+0][r]=b0.x; Bs[0][kqa+1][r]=b0.y; Bs[0][kqa+2][r]=b0.z; Bs[0][kqa+3][r]=b0.w;
    Bs[0][kqa+4][r]=b1.x; Bs[0][kqa+5][r]=b1.y; Bs[0][kqa+6][r]=b1.z; Bs[0][kqa+7][r]=b1.w;
    __syncthreads();

    for (int kt=0; kt<48; kt++){
        int cur = kt & 1;
        if (kt < 47){
            int ko = (kt+1)*16;
            a0 = *(const float4*)(Ag + ko);
            a1 = *(const float4*)(Ag + ko + 4);
            b0 = *(const float4*)(Bg + ko);
            b1 = *(const float4*)(Bg + ko + 4);
        }
        #pragma unroll
        for (int kk=0; kk<16; kk++){
            float4 av0 = *(const float4*)&As[cur][kk][tm];
            float4 av1 = *(const float4*)&As[cur][kk][tm+4];
            ull bp0 = *(const ull*)&Bs[cur][kk][tn2];
            ull bp1 = *(const ull*)&Bs[cur][kk][tn2+32];
            ull bp2 = *(const ull*)&Bs[cur][kk][tn2+64];
            ull bp3 = *(const ull*)&Bs[cur][kk][tn2+96];
            float am[8] = {av0.x,av0.y,av0.z,av0.w,av1.x,av1.y,av1.z,av1.w};
            #pragma unroll
            for (int i=0;i<8;i++){
                ull as_ = splat2(am[i]);
                ffma2(acc[i][0], as_, bp0);
                ffma2(acc[i][1], as_, bp1);
                ffma2(acc[i][2], as_, bp2);
                ffma2(acc[i][3], as_, bp3);
            }
        }
        if (kt < 47){
            int nx = 1 - cur;
            As[nx][kqa+0][r]=a0.x; As[nx][kqa+1][r]=a0.y; As[nx][kqa+2][r]=a0.z; As[nx][kqa+3][r]=a0.w;
            As[nx][kqa+4][r]=a1.x; As[nx][kqa+5][r]=a1.y; As[nx][kqa+6][r]=a1.z; As[nx][kqa+7][r]=a1.w;
            Bs[nx][kqa+0][r]=b0.x; Bs[nx][kqa+1][r]=b0.y; Bs[nx][kqa+2][r]=b0.z; Bs[nx][kqa+3][r]=b0.w;
            Bs[nx][kqa+4][r]=b1.x; Bs[nx][kqa+5][r]=b1.y; Bs[nx][kqa+6][r]=b1.z; Bs[nx][kqa+7][r]=b1.w;
            __syncthreads();
        }
    }

    #pragma unroll
    for (int i=0;i<8;i++){
        float* crow = C + (size_t)(m0+tm+i)*G4 + n0;
        #pragma unroll
        for (int j=0;j<4;j++){
            float2 v = unpack2(acc[i][j]);
            v.x += bias[n0+tn2+32*j];
            v.y += bias[n0+tn2+32*j+1];
            *(float2*)(crow + tn2 + 32*j) = v;
        }
    }
}

// ---------------- persistent bidirectional LSTM ----------------
// 128 blocks x 256 threads (8 warps), 1 block/SM via ~220KB smem.
// Warp w owns a 12-row k-sub-slice of each 96-row chunk; lane = cg(8) x mh(4);
// each lane: 8 m-rows x 6 cols (3 f32x2 accs). Weights & h read from smem ONCE
// per step (cg partitions cols, mh/cg broadcast elsewhere). 8-way cross-warp
// partial reduction per step through gred.
__global__ __launch_bounds__(256, 1) void k_lstm_pers(
    const float* __restrict__ Whf, const float* __restrict__ Whb)
{
    extern __shared__ float sm[];
    float* ws   = sm;                       // [768][48]        36864 floats
    float* hbuf = ws + HH*CPB;              // [2][96][32]       6144 floats
    float* gred = hbuf + 2*KCH*BB;          // [8][32][50]      12800 floats
    float* cst  = gred + 8*GWSZ;            // [384]              384 floats

    int tid = threadIdx.x;
    int bid = blockIdx.x;
    int d    = bid >> 6;
    int bid6 = bid & 63;
    int u0   = bid6 * UPB;
    const float* Wm = d ? Whb : Whf;
    int* flagd = g_flag[d];

    // stage weights: ws[k][c], c = g*UPB+uu
    for (int idx = tid; idx < CPB*(HH/4); idx += 256){
        int c  = idx / (HH/4);
        int kq = (idx % (HH/4)) * 4;
        int g = c / UPB, uu = c % UPB;
        float4 w = *(const float4*)(Wm + (size_t)(g*HH + u0 + uu)*HH + kq);
        ws[(kq+0)*CPB + c] = w.x;
        ws[(kq+1)*CPB + c] = w.y;
        ws[(kq+2)*CPB + c] = w.z;
        ws[(kq+3)*CPB + c] = w.w;
    }
    for (int i = tid; i < UPB*BB; i += 256) cst[i] = 0.f;
    __syncthreads();

    int warp  = tid >> 5;
    int lane  = tid & 31;
    int cg    = lane & 7;
    int mh    = lane >> 3;
    int mBase = mh * 8;
    int cBase = cg * 6;

    const float* xg_d = g_xg[d];
    int uu1 = tid >> 5, mm1 = tid & 31;          // cell pair 1: (uu1, mm1)
    int uu2 = 8 + (tid >> 5), mm2 = tid & 31;    // cell pair 2 (tid<128)

    for (int s = 0; s < WW; s++){
        int t = d ? (WW-1-s) : s;
        const float* hsrc = &g_hstate[s&1][d][0][0];
        float*       hdst = &g_hstate[(s+1)&1][d][0][0];

        // xg prefetch for cell phase
        float x1[4], x2[4];
        {
            const float* xb = xg_d + (size_t)(mm1*WW + t)*G4 + u0 + uu1;
            x1[0]=xb[0]; x1[1]=xb[HH]; x1[2]=xb[2*HH]; x1[3]=xb[3*HH];
        }
        if (tid < 128){
            const float* xb = xg_d + (size_t)(mm2*WW + t)*G4 + u0 + uu2;
            x2[0]=xb[0]; x2[1]=xb[HH]; x2[2]=xb[2*HH]; x2[3]=xb[3*HH];
        }

        // stage chunk 0
        float4 s0, s1, s2;
        {
            const float4* p = (const float4*)hsrc;
            s0 = __ldcg(&p[tid]); s1 = __ldcg(&p[tid+256]); s2 = __ldcg(&p[tid+512]);
            float4* q = (float4*)hbuf;
            q[tid]=s0; q[tid+256]=s1; q[tid+512]=s2;
        }
        __syncthreads();

        ull acc[8][3];
        #pragma unroll
        for (int mi=0;mi<8;mi++){ acc[mi][0]=0ull; acc[mi][1]=0ull; acc[mi][2]=0ull; }

        for (int ch=0; ch<NCH; ch++){
            int cur = ch & 1;
            if (ch < NCH-1){
                const float4* p = (const float4*)(hsrc + (ch+1)*KCH*BB);
                s0 = __ldcg(&p[tid]); s1 = __ldcg(&p[tid+256]); s2 = __ldcg(&p[tid+512]);
            }
            const float* hc = hbuf + cur*KCH*BB + (warp*KPW)*BB + mBase;
            const float* wc = ws + (ch*KCH + warp*KPW)*CPB + cBase;
            #pragma unroll
            for (int kk=0; kk<KPW; kk++){
                float4 h0 = *(const float4*)(hc + kk*BB);
                float4 h1 = *(const float4*)(hc + kk*BB + 4);
                ull w0 = *(const ull*)(wc + kk*CPB);
                ull w1 = *(const ull*)(wc + kk*CPB + 2);
                ull w2 = *(const ull*)(wc + kk*CPB + 4);
                ull a;
                a = splat2(h0.x); ffma2(acc[0][0],a,w0); ffma2(acc[0][1],a,w1); ffma2(acc[0][2],a,w2);
                a = splat2(h0.y); ffma2(acc[1][0],a,w0); ffma2(acc[1][1],a,w1); ffma2(acc[1][2],a,w2);
                a = splat2(h0.z); ffma2(acc[2][0],a,w0); ffma2(acc[2][1],a,w1); ffma2(acc[2][2],a,w2);
                a = splat2(h0.w); ffma2(acc[3][0],a,w0); ffma2(acc[3][1],a,w1); ffma2(acc[3][2],a,w2);
                a = splat2(h1.x); ffma2(acc[4][0],a,w0); ffma2(acc[4][1],a,w1); ffma2(acc[4][2],a,w2);
                a = splat2(h1.y); ffma2(acc[5][0],a,w0); ffma2(acc[5][1],a,w1); ffma2(acc[5][2],a,w2);
                a = splat2(h1.z); ffma2(acc[6][0],a,w0); ffma2(acc[6][1],a,w1); ffma2(acc[6][2],a,w2);
                a = splat2(h1.w); ffma2(acc[7][0],a,w0); ffma2(acc[7][1],a,w1); ffma2(acc[7][2],a,w2);
            }
            if (ch < NCH-1){
                float4* q = (float4*)(hbuf + (1-cur)*KCH*BB);
                q[tid]=s0; q[tid+256]=s1; q[tid+512]=s2;
            }
            __syncthreads();
        }

        // write per-warp partials: gred[warp][m][c] (pitch 50)
        {
            float* gr = gred + warp*GWSZ;
            #pragma unroll
            for (int mi=0;mi<8;mi++){
                float* row = gr + (mBase+mi)*GPITCH + cBase;
                #pragma unroll
                for (int p=0;p<3;p++)
                    *(float2*)(row + 2*p) = unpack2(acc[mi][p]);
            }
        }
        __syncthreads();

        // LSTM cell (reduce 8 partials + xg)
        {
            int base = mm1*GPITCH + uu1;
            float gi=x1[0], gf=x1[1], gg=x1[2], go=x1[3];
            #pragma unroll
            for (int w=0; w<8; w++){
                const float* g = gred + w*GWSZ + base;
                gi += g[0]; gf += g[UPB]; gg += g[2*UPB]; go += g[3*UPB];
            }
            float c0 = cst[uu1*BB + mm1];
            float cn = sigmoidf_(gf)*c0 + sigmoidf_(gi)*tanhf(gg);
            float h  = sigmoidf_(go)*tanhf(cn);
            cst[uu1*BB + mm1] = cn;
            hdst[(u0+uu1)*BB + mm1] = h;
            g_hs[d][(size_t)(mm1*WW + t)*HH + u0 + uu1] = h;
        }
        if (tid < 128){
            int base = mm2*GPITCH + uu2;
            float gi=x2[0], gf=x2[1], gg=x2[2], go=x2[3];
            #pragma unroll
            for (int w=0; w<8; w++){
                const float* g = gred + w*GWSZ + base;
                gi += g[0]; gf += g[UPB]; gg += g[2*UPB]; go += g[3*UPB];
            }
            float c0 = cst[uu2*BB + mm2];
            float cn = sigmoidf_(gf)*c0 + sigmoidf_(gi)*tanhf(gg);
            float h  = sigmoidf_(go)*tanhf(cn);
            cst[uu2*BB + mm2] = cn;
            hdst[(u0+uu2)*BB + mm2] = h;
            g_hs[d][(size_t)(mm2*WW + t)*HH + u0 + uu2] = h;
        }

        // inter-block barrier: per-block flag + poll-all (no atomic serialization)
        __threadfence();
        __syncthreads();
        if (tid == 0) atomicExch(&flagd[bid6], s+1);
        if (tid < 32){
            int tgt = s + 1;
            while (true){
                int a = __ldcg(&flagd[tid]);
                int b = __ldcg(&flagd[tid+32]);
                if (__all_sync(0xffffffffu, (a >= tgt) && (b >= tgt))) break;
                __nanosleep(32);
            }
        }
        __syncthreads();
        __threadfence();
    }
}

// ---------------- final: logits, softmax, argmax ----------------
__global__ void k_final(const float* __restrict__ Wl, const float* __restrict__ bl,
                        float* __restrict__ out, int out_size)
{
    int p    = blockIdx.x*(blockDim.x>>5) + (threadIdx.x>>5);
    int lane = threadIdx.x & 31;
    if (p >= MR) return;

    const float* hf = g_hs[0] + (size_t)p*HH;
    const float* hb = g_hs[1] + (size_t)p*HH;

    float lg[NNER];
    #pragma unroll
    for (int n=0;n<NNER;n++) lg[n]=0.f;

    for (int k=lane; k<HH; k+=32){
        float hv  = hf[k];
        float hv2 = hb[k];
        #pragma unroll
        for (int n=0;n<NNER;n++){
            lg[n] += Wl[n*2*HH + k]*hv + Wl[n*2*HH + HH + k]*hv2;
        }
    }
    #pragma unroll
    for (int n=0;n<NNER;n++){
        #pragma unroll
        for (int o=16;o;o>>=1) lg[n] += __shfl_xor_sync(0xffffffffu, lg[n], o);
    }
    if (lane==0){
        float mx = -1e30f;
        #pragma unroll
        for (int n=0;n<NNER;n++){ lg[n] += bl[n]; mx = fmaxf(mx, lg[n]); }
        float e[NNER], sum=0.f;
        #pragma unroll
        for (int n=0;n<NNER;n++){ e[n] = expf(lg[n]-mx); sum += e[n]; }
        float inv = 1.0f/sum;
        int best = 0; float bv = lg[0];
        #pragma unroll
        for (int n=1;n<NNER;n++){ if (lg[n] > bv){ bv = lg[n]; best = n; } }
        #pragma unroll
        for (int n=0;n<NNER;n++) out[p*NNER + n] = e[n]*inv;
        if (out_size >= MR*NNER + MR) out[MR*NNER + p] = (float)best;
    }
}

// ---------------- launch ----------------
extern "C" void kernel_launch(void* const* d_in, const int* in_sizes, int n_in,
                              void* d_out, int out_size)
{
    const float* bert = (const float*)d_in[0];
    const int*   wid  = (const int*)  d_in[1];
    const float* Wihf = (const float*)d_in[2];
    const float* Whhf = (const float*)d_in[3];
    const float* bf   = (const float*)d_in[4];
    const float* Wihb = (const float*)d_in[5];
    const float* Whhb = (const float*)d_in[6];
    const float* bbv  = (const float*)d_in[7];
    const float* Wlin = (const float*)d_in[8];
    const float* blin = (const float*)d_in[9];

    static int smem_set = 0;
    const int pers_smem = (HH*CPB + 2*KCH*BB + 8*GWSZ + UPB*BB) * (int)sizeof(float);
    if (!smem_set){
        cudaFuncSetAttribute(k_lstm_pers, cudaFuncAttributeMaxDynamicSharedMemorySize, pers_smem);
        smem_set = 1;
    }

    k_init<<<128, 256>>>();
    k_find<<<(BB*TT + 255)/256, 256>>>(wid);
    k_gather<<<MR, 192>>>(bert);
    k_gemm_xg<<<dim3(G4/128, MPAD/128, 2), 256>>>(Wihf, Wihb, bf, bbv);
    k_lstm_pers<<<NBLK, 256, pers_smem>>>(Whhf, Whhb);
    k_final<<<(MR + 3)/4, 128>>>(Wlin, blin, (float*)d_out, out_size);
}